// round 2
// baseline (speedup 1.0000x reference)
#include <cuda_runtime.h>

// Problem constants (match reference)
#define B_    64
#define H_    32
#define KVH_  8
#define D_    128
#define BS_   16
#define MB_   128
#define G_    4       // H_/KVH_
#define L_    2048
#define S_    8       // KV splits (flash-decoding)
#define CHUNK (L_ / S_)   // 256 positions per split
#define NWARP 8
#define NTHREADS 256
#define SCALE_ 0.08838834764831845f

// Split-KV scratch: unnormalized partials per (b, kvh, split, g).
// Static __device__ globals (no runtime allocation — harness rule).
__device__ float g_ms[B_][KVH_][S_][G_][2];        // {m, sum}  (512 KB)
__device__ float g_acc[B_][KVH_][S_][G_][D_];      // acc       (8 MB)

__global__ __launch_bounds__(NTHREADS)
void attn_decode_pass1(
    const float* __restrict__ q,      // [B, H*D]
    const float* __restrict__ knew,   // [B, KVH*D]
    const float* __restrict__ vnew,   // [B, KVH*D]
    const float* __restrict__ kc,     // [NB, BS, KVH, D]
    const float* __restrict__ vc,     // [NB, BS, KVH, D]
    const int*   __restrict__ bt,     // [B, MB]
    const int*   __restrict__ cl)     // [B]
{
    __shared__ int   s_bt[CHUNK / BS_];   // 16 blocks cover one chunk
    __shared__ float s_m[NWARP][G_];
    __shared__ float s_s[NWARP][G_];
    __shared__ float s_acc[NWARP][G_][D_];

    const int kvh  = blockIdx.x;
    const int b    = blockIdx.y;
    const int spl  = blockIdx.z;
    const int tid  = threadIdx.x;
    const int warp = tid >> 5;
    const int lane = tid & 31;

    const int ctx  = cl[b];
    const int n    = ctx + 1;                 // inclusive of new token
    const int base = spl * CHUNK;
    const int end  = min(n, base + CHUNK);

    if (base >= n) {                          // empty chunk: mark and leave
        if (tid < G_) {
            g_ms[b][kvh][spl][tid][0] = -INFINITY;
            g_ms[b][kvh][spl][tid][1] = 0.f;
        }
        return;
    }

    if (tid < CHUNK / BS_)
        s_bt[tid] = bt[b * MB_ + (base >> 4) + tid];
    __syncthreads();

    // Q for the G query heads served by this kv head (4 floats/lane/head)
    float4 q4[G_];
#pragma unroll
    for (int g = 0; g < G_; g++)
        q4[g] = *reinterpret_cast<const float4*>(
            q + (size_t)(b * H_ + kvh * G_ + g) * D_ + lane * 4);

    float  m[G_], ssum[G_];
    float4 acc[G_];
#pragma unroll
    for (int g = 0; g < G_; g++) {
        m[g] = -INFINITY; ssum[g] = 0.f;
        acc[g] = make_float4(0.f, 0.f, 0.f, 0.f);
    }

    const int newoff = (b * KVH_ + kvh) * D_ + lane * 4;

    // ---- main loop: warp w owns positions l = base + w + 8i ----
    int l = base + warp;
    float4 kk, vv;
    if (l < end) {
        if (l == ctx) {
            kk = *reinterpret_cast<const float4*>(knew + newoff);
            vv = *reinterpret_cast<const float4*>(vnew + newoff);
        } else {
            int li = l - base;
            int idx = ((s_bt[li >> 4] * BS_ + (l & (BS_ - 1))) * KVH_ + kvh) * D_ + lane * 4;
            kk = *reinterpret_cast<const float4*>(kc + idx);
            vv = *reinterpret_cast<const float4*>(vc + idx);
        }
    }

    while (l < end) {
        const int ln = l + NWARP;
        float4 kn, vn;
        if (ln < end) {     // prefetch next position before current math
            if (ln == ctx) {
                kn = *reinterpret_cast<const float4*>(knew + newoff);
                vn = *reinterpret_cast<const float4*>(vnew + newoff);
            } else {
                int li = ln - base;
                int idx = ((s_bt[li >> 4] * BS_ + (ln & (BS_ - 1))) * KVH_ + kvh) * D_ + lane * 4;
                kn = *reinterpret_cast<const float4*>(kc + idx);
                vn = *reinterpret_cast<const float4*>(vc + idx);
            }
        }

#pragma unroll
        for (int g = 0; g < G_; g++) {
            float d = kk.x * q4[g].x + kk.y * q4[g].y
                    + kk.z * q4[g].z + kk.w * q4[g].w;
#pragma unroll
            for (int off = 16; off; off >>= 1)
                d += __shfl_xor_sync(0xffffffffu, d, off);
            const float sc = d * SCALE_;

            if (sc > m[g]) {                   // warp-uniform, rare
                const float corr = __expf(m[g] - sc);
                m[g]    = sc;
                ssum[g] = ssum[g] * corr + 1.f;
                acc[g].x = acc[g].x * corr + vv.x;
                acc[g].y = acc[g].y * corr + vv.y;
                acc[g].z = acc[g].z * corr + vv.z;
                acc[g].w = acc[g].w * corr + vv.w;
            } else {
                const float p = __expf(sc - m[g]);
                ssum[g] += p;
                acc[g].x += p * vv.x;
                acc[g].y += p * vv.y;
                acc[g].z += p * vv.z;
                acc[g].w += p * vv.w;
            }
        }
        kk = kn; vv = vn; l = ln;
    }

    // ---- combine the 8 warps' partials, store chunk partial to scratch ----
#pragma unroll
    for (int g = 0; g < G_; g++) {
        *reinterpret_cast<float4*>(&s_acc[warp][g][lane * 4]) = acc[g];
        if (lane == 0) { s_m[warp][g] = m[g]; s_s[warp][g] = ssum[g]; }
    }
    __syncthreads();

#pragma unroll
    for (int e = tid; e < G_ * D_; e += NTHREADS) {
        const int g = e >> 7;         // /128
        const int d = e & (D_ - 1);
        float M = -INFINITY;
#pragma unroll
        for (int w = 0; w < NWARP; w++) M = fmaxf(M, s_m[w][g]);
        float S = 0.f, num = 0.f;
#pragma unroll
        for (int w = 0; w < NWARP; w++) {
            const float ew = __expf(s_m[w][g] - M);   // 0 for empty warps
            S   += ew * s_s[w][g];
            num += ew * s_acc[w][g][d];
        }
        g_acc[b][kvh][spl][g][d] = num;
        if (d == 0) {
            g_ms[b][kvh][spl][g][0] = M;
            g_ms[b][kvh][spl][g][1] = S;
        }
    }
}

__global__ __launch_bounds__(NTHREADS)
void attn_decode_pass2(float* __restrict__ out)   // [B, H*D]
{
    const int idx = blockIdx.x * NTHREADS + threadIdx.x;  // < B*KVH*G*D
    const int d   = idx & (D_ - 1);
    const int g   = (idx >> 7) & (G_ - 1);
    const int kvh = (idx >> 9) & (KVH_ - 1);
    const int b   = idx >> 12;

    float M = -INFINITY;
#pragma unroll
    for (int s = 0; s < S_; s++)
        M = fmaxf(M, g_ms[b][kvh][s][g][0]);

    float S = 0.f, num = 0.f;
#pragma unroll
    for (int s = 0; s < S_; s++) {
        const float ms = g_ms[b][kvh][s][g][0];
        if (ms == -INFINITY) continue;   // empty chunk: acc is garbage, skip
        const float ew = __expf(ms - M);
        S   += ew * g_ms[b][kvh][s][g][1];
        num += ew * g_acc[b][kvh][s][g][d];
    }
    out[(size_t)(b * H_ + kvh * G_ + g) * D_ + d] = num / S;
}

extern "C" void kernel_launch(void* const* d_in, const int* in_sizes, int n_in,
                              void* d_out, int out_size)
{
    const float* q   = (const float*)d_in[0];
    const float* k   = (const float*)d_in[1];
    const float* v   = (const float*)d_in[2];
    const float* kc  = (const float*)d_in[3];
    const float* vc  = (const float*)d_in[4];
    const int*   bt  = (const int*)d_in[5];
    const int*   cl  = (const int*)d_in[6];
    float*       out = (float*)d_out;

    dim3 grid1(KVH_, B_, S_);
    attn_decode_pass1<<<grid1, NTHREADS>>>(q, k, v, kc, vc, bt, cl);

    const int total = B_ * KVH_ * G_ * D_;           // 262144
    attn_decode_pass2<<<total / NTHREADS, NTHREADS>>>(out);
}

// round 3
// speedup vs baseline: 1.3751x; 1.3751x over previous
#include <cuda_runtime.h>

// Problem constants (match reference)
#define B_    64
#define H_    32
#define KVH_  8
#define D_    128
#define BS_   16
#define MB_   128
#define G_    4       // H_/KVH_
#define L_    2048
#define S_    8       // KV splits (flash-decoding)
#define CHUNK (L_ / S_)   // 256 positions per split
#define NWARP 8
#define NTHREADS 256
#define SCALE_ 0.08838834764831845f

// Split-KV scratch (no-max softmax => plain unnormalized sums).
__device__ float g_sum[B_][KVH_][S_][G_];          //  8 KB
__device__ float g_acc[B_][KVH_][S_][G_][D_];      //  8 MB

__global__ __launch_bounds__(NTHREADS)
void attn_decode_pass1(
    const float* __restrict__ q,      // [B, H*D]
    const float* __restrict__ knew,   // [B, KVH*D]
    const float* __restrict__ vnew,   // [B, KVH*D]
    const float* __restrict__ kc,     // [NB, BS, KVH, D]
    const float* __restrict__ vc,     // [NB, BS, KVH, D]
    const int*   __restrict__ bt,     // [B, MB]
    const int*   __restrict__ cl)     // [B]
{
    __shared__ int   s_bt[CHUNK / BS_];
    __shared__ float s_s[NWARP][G_];
    __shared__ float s_acc[NWARP][G_][D_];

    const int kvh  = blockIdx.x;
    const int b    = blockIdx.y;
    const int spl  = blockIdx.z;
    const int tid  = threadIdx.x;
    const int warp = tid >> 5;
    const int lane = tid & 31;

    const int ctx  = cl[b];
    const int n    = ctx + 1;
    const int base = spl * CHUNK;
    const int end  = min(n, base + CHUNK);

    if (base >= n) {                   // empty chunk: mark and leave
        if (tid < G_) g_sum[b][kvh][spl][tid] = 0.f;
        return;
    }

    if (tid < CHUNK / BS_)
        s_bt[tid] = bt[b * MB_ + (base >> 4) + tid];
    __syncthreads();

    float4 q4[G_];
#pragma unroll
    for (int g = 0; g < G_; g++)
        q4[g] = *reinterpret_cast<const float4*>(
            q + (size_t)(b * H_ + kvh * G_ + g) * D_ + lane * 4);

    float  ssum[G_];
    float4 acc[G_];
#pragma unroll
    for (int g = 0; g < G_; g++) {
        ssum[g] = 0.f;
        acc[g] = make_float4(0.f, 0.f, 0.f, 0.f);
    }

    const int newoff = (b * KVH_ + kvh) * D_ + lane * 4;

    // Load one position's K,V (zero-filled when invalid)
    auto loadkv = [&](int l, bool valid, float4& kk, float4& vv) {
        kk = make_float4(0.f, 0.f, 0.f, 0.f);
        vv = make_float4(0.f, 0.f, 0.f, 0.f);
        if (!valid) return;
        if (l == ctx) {
            kk = *reinterpret_cast<const float4*>(knew + newoff);
            vv = *reinterpret_cast<const float4*>(vnew + newoff);
        } else {
            int li  = l - base;
            int idx = ((s_bt[li >> 4] * BS_ + (l & (BS_ - 1))) * KVH_ + kvh) * D_ + lane * 4;
            kk = *reinterpret_cast<const float4*>(kc + idx);
            vv = *reinterpret_cast<const float4*>(vc + idx);
        }
    };

    // ---- main loop: warp w owns position pairs (base+2w+16i, +1) ----
    int l0 = base + warp * 2;
    float4 k0, v0, k1, v1;
    bool val0 = l0 < end, val1 = (l0 + 1) < end;
    loadkv(l0,     val0, k0, v0);
    loadkv(l0 + 1, val1, k1, v1);

    while (l0 < end) {
        const int ln = l0 + 2 * NWARP;
        float4 nk0, nv0, nk1, nv1;
        const bool nval0 = ln < end, nval1 = (ln + 1) < end;
        loadkv(ln,     nval0, nk0, nv0);   // prefetch next pair
        loadkv(ln + 1, nval1, nk1, nv1);

        // 8 independent dot/reduce chains, interleaved
        float d0[G_], d1[G_];
#pragma unroll
        for (int g = 0; g < G_; g++) {
            d0[g] = k0.x * q4[g].x + k0.y * q4[g].y + k0.z * q4[g].z + k0.w * q4[g].w;
            d1[g] = k1.x * q4[g].x + k1.y * q4[g].y + k1.z * q4[g].z + k1.w * q4[g].w;
        }
#pragma unroll
        for (int off = 16; off; off >>= 1) {
#pragma unroll
            for (int g = 0; g < G_; g++) {
                d0[g] += __shfl_xor_sync(0xffffffffu, d0[g], off);
                d1[g] += __shfl_xor_sync(0xffffffffu, d1[g], off);
            }
        }
#pragma unroll
        for (int g = 0; g < G_; g++) {
            const float p0 = val0 ? __expf(d0[g] * SCALE_) : 0.f;
            const float p1 = val1 ? __expf(d1[g] * SCALE_) : 0.f;
            ssum[g] += p0 + p1;
            acc[g].x += p0 * v0.x + p1 * v1.x;
            acc[g].y += p0 * v0.y + p1 * v1.y;
            acc[g].z += p0 * v0.z + p1 * v1.z;
            acc[g].w += p0 * v0.w + p1 * v1.w;
        }

        k0 = nk0; v0 = nv0; k1 = nk1; v1 = nv1;
        val0 = nval0; val1 = nval1; l0 = ln;
    }

    // ---- combine the 8 warps' partials (plain sums), store to scratch ----
#pragma unroll
    for (int g = 0; g < G_; g++) {
        *reinterpret_cast<float4*>(&s_acc[warp][g][lane * 4]) = acc[g];
        if (lane == 0) s_s[warp][g] = ssum[g];
    }
    __syncthreads();

#pragma unroll
    for (int e = tid; e < G_ * D_; e += NTHREADS) {
        const int g = e >> 7;
        const int d = e & (D_ - 1);
        float S = 0.f, num = 0.f;
#pragma unroll
        for (int w = 0; w < NWARP; w++) {
            S   += s_s[w][g];
            num += s_acc[w][g][d];
        }
        g_acc[b][kvh][spl][g][d] = num;
        if (d == 0) g_sum[b][kvh][spl][g] = S;
    }
}

__global__ __launch_bounds__(NTHREADS)
void attn_decode_pass2(float* __restrict__ out)   // [B, H*D]
{
    const int idx = blockIdx.x * NTHREADS + threadIdx.x;
    const int d   = idx & (D_ - 1);
    const int g   = (idx >> 7) & (G_ - 1);
    const int kvh = (idx >> 9) & (KVH_ - 1);
    const int b   = idx >> 12;

    float S = 0.f, num = 0.f;
#pragma unroll
    for (int s = 0; s < S_; s++) {
        const float ss = g_sum[b][kvh][s][g];
        if (ss != 0.f) {                 // skip empty chunks (acc undefined)
            S   += ss;
            num += g_acc[b][kvh][s][g][d];
        }
    }
    out[(size_t)(b * H_ + kvh * G_ + g) * D_ + d] = num / S;
}

extern "C" void kernel_launch(void* const* d_in, const int* in_sizes, int n_in,
                              void* d_out, int out_size)
{
    const float* q   = (const float*)d_in[0];
    const float* k   = (const float*)d_in[1];
    const float* v   = (const float*)d_in[2];
    const float* kc  = (const float*)d_in[3];
    const float* vc  = (const float*)d_in[4];
    const int*   bt  = (const int*)d_in[5];
    const int*   cl  = (const int*)d_in[6];
    float*       out = (float*)d_out;

    dim3 grid1(KVH_, B_, S_);
    attn_decode_pass1<<<grid1, NTHREADS>>>(q, k, v, kc, vc, bt, cl);

    const int total = B_ * KVH_ * G_ * D_;           // 262144
    attn_decode_pass2<<<total / NTHREADS, NTHREADS>>>(out);
}